// round 1
// baseline (speedup 1.0000x reference)
#include <cuda_runtime.h>
#include <cuda_bf16.h>

// out[b,k] = sum_{i,j} x[b,i] * W[k,i,j] * x[b,j]
// Strategy:
//   prep kernel: Wp[t][k] = W[k,i,i] (i==j) or W[k,i,j]+W[k,j,i] (i<j),
//                t enumerates pairs (i<=j) lexicographically, 136 pairs, k fast.
//   main kernel: 1 thread per batch row. s_t = x_i*x_j once, then 16 k-channels
//                updated as 8 packed f32x2 FMAs (Blackwell FFMA2 via PTX).

#define NPAIR 136
#define WP_ELEMS (NPAIR * 16)

__device__ float d_Wp[WP_ELEMS];

typedef unsigned long long ull;

__device__ __forceinline__ ull pack2(float lo, float hi) {
    ull r;
    asm("mov.b64 %0, {%1, %2};" : "=l"(r) : "f"(lo), "f"(hi));
    return r;
}

__device__ __forceinline__ ull mul2(ull a, ull b) {
    ull r;
    asm("mul.rn.f32x2 %0, %1, %2;" : "=l"(r) : "l"(a), "l"(b));
    return r;
}

__device__ __forceinline__ ull ffma2(ull a, ull b, ull c) {
    ull r;
    asm("fma.rn.f32x2 %0, %1, %2, %3;" : "=l"(r) : "l"(a), "l"(b), "l"(c));
    return r;
}

__global__ void prep_kernel(const float* __restrict__ W) {
    int idx = blockIdx.x * blockDim.x + threadIdx.x;
    if (idx >= WP_ELEMS) return;
    int t = idx >> 4;
    int k = idx & 15;
    // decode t -> (i, j) with i <= j, lexicographic
    int i = 0, rem = t;
    while (rem >= 16 - i) { rem -= 16 - i; ++i; }
    int j = i + rem;
    float v = W[k * 256 + i * 16 + j];
    if (i != j) v += W[k * 256 + j * 16 + i];
    d_Wp[idx] = v;
}

__global__ void __launch_bounds__(256, 4)
bilinear_kernel(const float* __restrict__ x, float* __restrict__ out) {
    __shared__ __align__(16) float sW[WP_ELEMS];
    for (int idx = threadIdx.x; idx < WP_ELEMS; idx += 256)
        sW[idx] = d_Wp[idx];
    __syncthreads();

    unsigned int b = blockIdx.x * 256u + threadIdx.x;
    const float4* xr = (const float4*)(x + (size_t)b * 16);
    float4 a0 = xr[0];
    float4 a1 = xr[1];
    float4 a2 = xr[2];
    float4 a3 = xr[3];

    // xp[i] = (x_i, x_i) packed
    ull xp[16];
    xp[0]  = pack2(a0.x, a0.x); xp[1]  = pack2(a0.y, a0.y);
    xp[2]  = pack2(a0.z, a0.z); xp[3]  = pack2(a0.w, a0.w);
    xp[4]  = pack2(a1.x, a1.x); xp[5]  = pack2(a1.y, a1.y);
    xp[6]  = pack2(a1.z, a1.z); xp[7]  = pack2(a1.w, a1.w);
    xp[8]  = pack2(a2.x, a2.x); xp[9]  = pack2(a2.y, a2.y);
    xp[10] = pack2(a2.z, a2.z); xp[11] = pack2(a2.w, a2.w);
    xp[12] = pack2(a3.x, a3.x); xp[13] = pack2(a3.y, a3.y);
    xp[14] = pack2(a3.z, a3.z); xp[15] = pack2(a3.w, a3.w);

    // acc[p] holds packed (out[2p], out[2p+1])
    ull acc[8];
#pragma unroll
    for (int p = 0; p < 8; ++p) acc[p] = 0ull;

    int t = 0;
#pragma unroll
    for (int i = 0; i < 16; ++i) {
#pragma unroll
        for (int j = i; j < 16; ++j) {
            ull s2 = mul2(xp[i], xp[j]);  // (x_i*x_j, x_i*x_j)
            const ulonglong2* wrow = (const ulonglong2*)(sW + t * 16);
            ulonglong2 w0 = wrow[0];
            ulonglong2 w1 = wrow[1];
            ulonglong2 w2 = wrow[2];
            ulonglong2 w3 = wrow[3];
            acc[0] = ffma2(w0.x, s2, acc[0]);
            acc[1] = ffma2(w0.y, s2, acc[1]);
            acc[2] = ffma2(w1.x, s2, acc[2]);
            acc[3] = ffma2(w1.y, s2, acc[3]);
            acc[4] = ffma2(w2.x, s2, acc[4]);
            acc[5] = ffma2(w2.y, s2, acc[5]);
            acc[6] = ffma2(w3.x, s2, acc[6]);
            acc[7] = ffma2(w3.y, s2, acc[7]);
            ++t;
        }
    }

    ulonglong2* op = (ulonglong2*)(out + (size_t)b * 16);
    op[0] = make_ulonglong2(acc[0], acc[1]);
    op[1] = make_ulonglong2(acc[2], acc[3]);
    op[2] = make_ulonglong2(acc[4], acc[5]);
    op[3] = make_ulonglong2(acc[6], acc[7]);
}

extern "C" void kernel_launch(void* const* d_in, const int* in_sizes, int n_in,
                              void* d_out, int out_size) {
    const float* x = (const float*)d_in[0];
    const float* W = (const float*)d_in[1];
    // Defensive: identify W by its size (16*16*16 = 4096 elements)
    if (n_in >= 2 && in_sizes[0] == 4096) {
        W = (const float*)d_in[0];
        x = (const float*)d_in[1];
    }
    float* out = (float*)d_out;

    prep_kernel<<<(WP_ELEMS + 255) / 256, 256>>>(W);

    const unsigned int B = 1048576u;
    bilinear_kernel<<<B / 256, 256>>>(x, out);
}

// round 2
// speedup vs baseline: 1.5503x; 1.5503x over previous
#include <cuda_runtime.h>
#include <cuda_bf16.h>

// out[b,k] = sum_{i,j} x[b,i] * W[k,i,j] * x[b,j]
// prep: Wp[t][k] = W[k,i,i] (i==j) or W[k,i,j]+W[k,j,i] (i<j), t = pair index (i<=j).
// main: 2 batch rows per thread; per pair, 4 broadcast LDS.128 of W feed
//       16 packed f32x2 FMAs (8 per row) -> 4 fma per LDS instead of 2.

#define NPAIR 136
#define WP_ELEMS (NPAIR * 16)

__device__ float d_Wp[WP_ELEMS];

typedef unsigned long long ull;

__device__ __forceinline__ ull pack2(float lo, float hi) {
    ull r;
    asm("mov.b64 %0, {%1, %2};" : "=l"(r) : "f"(lo), "f"(hi));
    return r;
}

__device__ __forceinline__ ull ffma2(ull a, ull b, ull c) {
    ull r;
    asm("fma.rn.f32x2 %0, %1, %2, %3;" : "=l"(r) : "l"(a), "l"(b), "l"(c));
    return r;
}

__global__ void prep_kernel(const float* __restrict__ W) {
    int idx = blockIdx.x * blockDim.x + threadIdx.x;
    if (idx >= WP_ELEMS) return;
    int t = idx >> 4;
    int k = idx & 15;
    int i = 0, rem = t;
    while (rem >= 16 - i) { rem -= 16 - i; ++i; }
    int j = i + rem;
    float v = W[k * 256 + i * 16 + j];
    if (i != j) v += W[k * 256 + j * 16 + i];
    d_Wp[idx] = v;
}

__global__ void __launch_bounds__(256, 2)
bilinear_kernel(const float* __restrict__ x, float* __restrict__ out) {
    __shared__ __align__(16) float sW[WP_ELEMS];
    for (int idx = threadIdx.x; idx < WP_ELEMS; idx += 256)
        sW[idx] = d_Wp[idx];
    __syncthreads();

    // two rows per thread: b0 = base + tid, b1 = base + tid + 256 (both coalesced)
    unsigned int base = blockIdx.x * 512u;
    unsigned int b0 = base + threadIdx.x;
    unsigned int b1 = b0 + 256u;

    float x0[16], x1[16];
    {
        const float4* r0 = (const float4*)(x + (size_t)b0 * 16);
        const float4* r1 = (const float4*)(x + (size_t)b1 * 16);
#pragma unroll
        for (int q = 0; q < 4; ++q) {
            float4 v0 = r0[q];
            float4 v1 = r1[q];
            x0[q * 4 + 0] = v0.x; x0[q * 4 + 1] = v0.y;
            x0[q * 4 + 2] = v0.z; x0[q * 4 + 3] = v0.w;
            x1[q * 4 + 0] = v1.x; x1[q * 4 + 1] = v1.y;
            x1[q * 4 + 2] = v1.z; x1[q * 4 + 3] = v1.w;
        }
    }

    // acc{r}[p] holds packed (out[2p], out[2p+1]) for row r
    ull acc0[8], acc1[8];
#pragma unroll
    for (int p = 0; p < 8; ++p) { acc0[p] = 0ull; acc1[p] = 0ull; }

    int t = 0;
#pragma unroll
    for (int i = 0; i < 16; ++i) {
#pragma unroll
        for (int j = i; j < 16; ++j) {
            float s0 = x0[i] * x0[j];
            float s1 = x1[i] * x1[j];
            ull s0p = pack2(s0, s0);
            ull s1p = pack2(s1, s1);
            const ulonglong2* wrow = (const ulonglong2*)(sW + t * 16);
            ulonglong2 w0 = wrow[0];
            ulonglong2 w1 = wrow[1];
            ulonglong2 w2 = wrow[2];
            ulonglong2 w3 = wrow[3];
            acc0[0] = ffma2(w0.x, s0p, acc0[0]);
            acc0[1] = ffma2(w0.y, s0p, acc0[1]);
            acc0[2] = ffma2(w1.x, s0p, acc0[2]);
            acc0[3] = ffma2(w1.y, s0p, acc0[3]);
            acc0[4] = ffma2(w2.x, s0p, acc0[4]);
            acc0[5] = ffma2(w2.y, s0p, acc0[5]);
            acc0[6] = ffma2(w3.x, s0p, acc0[6]);
            acc0[7] = ffma2(w3.y, s0p, acc0[7]);
            acc1[0] = ffma2(w0.x, s1p, acc1[0]);
            acc1[1] = ffma2(w0.y, s1p, acc1[1]);
            acc1[2] = ffma2(w1.x, s1p, acc1[2]);
            acc1[3] = ffma2(w1.y, s1p, acc1[3]);
            acc1[4] = ffma2(w2.x, s1p, acc1[4]);
            acc1[5] = ffma2(w2.y, s1p, acc1[5]);
            acc1[6] = ffma2(w3.x, s1p, acc1[6]);
            acc1[7] = ffma2(w3.y, s1p, acc1[7]);
            ++t;
        }
    }

    ulonglong2* o0 = (ulonglong2*)(out + (size_t)b0 * 16);
    ulonglong2* o1 = (ulonglong2*)(out + (size_t)b1 * 16);
    o0[0] = make_ulonglong2(acc0[0], acc0[1]);
    o0[1] = make_ulonglong2(acc0[2], acc0[3]);
    o0[2] = make_ulonglong2(acc0[4], acc0[5]);
    o0[3] = make_ulonglong2(acc0[6], acc0[7]);
    o1[0] = make_ulonglong2(acc1[0], acc1[1]);
    o1[1] = make_ulonglong2(acc1[2], acc1[3]);
    o1[2] = make_ulonglong2(acc1[4], acc1[5]);
    o1[3] = make_ulonglong2(acc1[6], acc1[7]);
}

extern "C" void kernel_launch(void* const* d_in, const int* in_sizes, int n_in,
                              void* d_out, int out_size) {
    const float* x = (const float*)d_in[0];
    const float* W = (const float*)d_in[1];
    if (n_in >= 2 && in_sizes[0] == 4096) {  // defensive input identification
        W = (const float*)d_in[0];
        x = (const float*)d_in[1];
    }
    float* out = (float*)d_out;

    prep_kernel<<<(WP_ELEMS + 255) / 256, 256>>>(W);

    const unsigned int B = 1048576u;
    bilinear_kernel<<<B / 512, 256>>>(x, out);
}